// round 8
// baseline (speedup 1.0000x reference)
#include <cuda_runtime.h>
#include <cuda_fp16.h>
#include <cstdint>

// NearestNeighborGraph: 16 samples x 2048 points x 64 dims, K=16.
// Output (float32): [knn_dist | dst | src], each 16*2048*16.
//
// Gram matrix via mma.sync m16n8k16 fp16 with 2-term error-split
// (x = xh + xl in fp16; x*y ~= xh*yh + xh*yl + xl*yh, fp32-grade).
// NOTE: harness compiles PTX at compute_103 (no 'a'), so tcgen05 is
// unavailable; mma.sync/ldmatrix are the legal tensor-core path.

#define NS     16
#define NP     2048
#define DIMS   64
#define KNN    16
#define TM     128
#define TN     128
#define NTILES (NP / TN)
#define OUTBLK (NS * NP * KNN)

#define PITCHB 144           // bytes per row (72 halves): 9x16B, ldmatrix conflict-free
#define PITCHQ 9             // uint4 per row
#define TILEQ  (TM * PITCHQ) // 1152 uint4 = 18432 B per term tile

// SMEM layout (bytes)
#define SM_AH  0
#define SM_AL  18432
#define SM_BH  36864
#define SM_BL  55296
#define SM_CN  73728
#define SM_TOT 74240
// keys overlay (after MMA phase): 128 rows * 4 lanes * 16 keys * 8B = 64KB at offset 0

__device__ uint4 g_h16[NS * NP * PITCHQ];  // fp16 hi plane, 144B pitch
__device__ uint4 g_l16[NS * NP * PITCHQ];  // fp16 lo plane
__device__ float g_x2[NS * NP];            // fp32 norms

// ---------------- helpers ----------------
__device__ __forceinline__ uint32_t smem_u32(const void* p) {
    uint32_t a;
    asm("{ .reg .u64 t; cvta.to.shared.u64 t, %1; cvt.u32.u64 %0, t; }"
        : "=r"(a) : "l"(p));
    return a;
}

__device__ __forceinline__ void ldsm4(uint32_t* r, uint32_t addr) {
    asm volatile("ldmatrix.sync.aligned.m8n8.x4.shared.b16 {%0,%1,%2,%3}, [%4];"
                 : "=r"(r[0]), "=r"(r[1]), "=r"(r[2]), "=r"(r[3]) : "r"(addr));
}

__device__ __forceinline__ void mma16816(float* d, const uint32_t* a,
                                         const uint32_t* b) {
    asm volatile(
        "mma.sync.aligned.m16n8k16.row.col.f32.f16.f16.f32 "
        "{%0,%1,%2,%3}, {%4,%5,%6,%7}, {%8,%9}, {%0,%1,%2,%3};"
        : "+f"(d[0]), "+f"(d[1]), "+f"(d[2]), "+f"(d[3])
        : "r"(a[0]), "r"(a[1]), "r"(a[2]), "r"(a[3]), "r"(b[0]), "r"(b[1]));
}

__device__ __forceinline__ uint32_t pack_h2(__half lo, __half hi) {
    __half2 h = __halves2half2(lo, hi);  // lo in low 16 bits
    return *reinterpret_cast<uint32_t*>(&h);
}

// Insert (dist, idx) into an ascending sorted list of packed keys.
// ord(float) transform makes u32 compare match float compare; idx in low
// bits breaks ties toward the smaller index (lax.top_k stable order).
#define INSERT(tk, dval, idx) do {                                             \
    uint32_t _u = __float_as_uint(dval);                                       \
    _u ^= (uint32_t)((int)_u >> 31) | 0x80000000u;                             \
    unsigned long long _key =                                                  \
        ((unsigned long long)_u << 32) | (uint32_t)(idx);                      \
    if (_key < (tk)[KNN - 1]) {                                                \
        (tk)[KNN - 1] = _key;                                                  \
        _Pragma("unroll")                                                      \
        for (int _t = KNN - 1; _t > 0; --_t) {                                 \
            if ((tk)[_t] < (tk)[_t - 1]) {                                     \
                unsigned long long _tmp = (tk)[_t];                            \
                (tk)[_t] = (tk)[_t - 1];                                       \
                (tk)[_t - 1] = _tmp;                                           \
            }                                                                  \
        }                                                                      \
    }                                                                          \
} while (0)

// ---------------- prologue: fp16 split planes + norms ----------------
__global__ void __launch_bounds__(256) prep_kernel(const float* __restrict__ h) {
    int r = blockIdx.x * blockDim.x + threadIdx.x;
    if (r >= NS * NP) return;
    const float4* src = reinterpret_cast<const float4*>(h + (size_t)r * DIMS);
    float s = 0.f;
#pragma unroll
    for (int q = 0; q < 8; ++q) {  // 8 output uint4 = 8 halves each
        float4 x0 = src[2 * q];
        float4 x1 = src[2 * q + 1];
        float f[8] = {x0.x, x0.y, x0.z, x0.w, x1.x, x1.y, x1.z, x1.w};
        uint32_t rh[4], rl[4];
#pragma unroll
        for (int e = 0; e < 4; ++e) {
            float a = f[2 * e], c = f[2 * e + 1];
            __half ah = __float2half_rn(a), ch = __float2half_rn(c);
            float al = a - __half2float(ah);
            float cl = c - __half2float(ch);
            rh[e] = pack_h2(ah, ch);
            rl[e] = pack_h2(__float2half_rn(al), __float2half_rn(cl));
            s += a * a;
            s += c * c;
        }
        g_h16[(size_t)r * PITCHQ + q] = make_uint4(rh[0], rh[1], rh[2], rh[3]);
        g_l16[(size_t)r * PITCHQ + q] = make_uint4(rl[0], rl[1], rl[2], rl[3]);
    }
    g_h16[(size_t)r * PITCHQ + 8] = make_uint4(0, 0, 0, 0);  // pad (never read)
    g_l16[(size_t)r * PITCHQ + 8] = make_uint4(0, 0, 0, 0);
    g_x2[r] = s;
}

// ---------------- main kernel ----------------
__global__ void __launch_bounds__(256) knn_kernel(float* __restrict__ out,
                                                  int write_edges) {
    extern __shared__ char smem[];
    const uint32_t sb = smem_u32(smem);
    const int tid  = threadIdx.x;
    const int w    = tid >> 5;
    const int lane = tid & 31;
    const int tg   = lane & 3;   // thread-in-group (n/col selector)
    const int g    = lane >> 2;  // group id (row selector)
    const int b    = blockIdx.y;
    const int qbase = blockIdx.x * TM;  // query base within sample

    // ---- stage A (query) tiles: flat uint4 copy, both terms ----
    {
        const uint4* srcH = g_h16 + (size_t)(b * NP + qbase) * PITCHQ;
        const uint4* srcL = g_l16 + (size_t)(b * NP + qbase) * PITCHQ;
        uint4* dA = reinterpret_cast<uint4*>(smem);
        for (int i = tid; i < TILEQ; i += 256) {
            dA[i]         = srcH[i];           // A_h at SM_AH
            dA[TILEQ + i] = srcL[i];           // A_l at SM_AL
        }
    }
    __syncthreads();

    // ---- cache A fragments (queries fixed for whole CTA) ----
    // ldmatrix x4 lane mapping: row = lane%16, col-halves = (lane/16)*8
    uint32_t Ah[4][4], Al[4][4];
    {
        uint32_t a_off = sb + SM_AH + (uint32_t)(w * 16 + (lane & 15)) * PITCHB +
                         (uint32_t)(lane >> 4) * 16;
#pragma unroll
        for (int k = 0; k < 4; ++k) {
            ldsm4(Ah[k], a_off + k * 32);
            ldsm4(Al[k], a_off + (SM_AL - SM_AH) + k * 32);
        }
    }
    const int row0 = w * 16 + g;           // this lane's first output row
    const float qn0 = g_x2[b * NP + qbase + row0];
    const float qn1 = g_x2[b * NP + qbase + row0 + 8];

    unsigned long long tk0[KNN], tk1[KNN];
#pragma unroll
    for (int k = 0; k < KNN; ++k) { tk0[k] = ~0ull; tk1[k] = ~0ull; }

    // B ldmatrix per-lane offset: n_local = (lane%8) + (lane>=16)*8,
    // k-offset 16B when lane&8 (second 8x8 along k).
    const uint32_t b_lane_off =
        (uint32_t)(((lane & 7) + ((lane >> 4) << 3)) * PITCHB) +
        ((lane & 8) ? 16u : 0u);
    const float* cn = reinterpret_cast<const float*>(smem + SM_CN);

    for (int tt = 0; tt < NTILES; ++tt) {
        __syncthreads();  // previous tile's cn reads done
        {
            const uint4* sH = g_h16 + (size_t)(b * NP + tt * TN) * PITCHQ;
            const uint4* sL = g_l16 + (size_t)(b * NP + tt * TN) * PITCHQ;
            uint4* dB = reinterpret_cast<uint4*>(smem + SM_BH);
            for (int i = tid; i < TILEQ; i += 256) {
                dB[i]         = sH[i];
                dB[TILEQ + i] = sL[i];
            }
            if (tid < TN)
                reinterpret_cast<float*>(smem + SM_CN)[tid] =
                    g_x2[b * NP + tt * TN + tid];
        }
        __syncthreads();

        float acc[16][4];
#pragma unroll
        for (int nt = 0; nt < 16; ++nt)
#pragma unroll
            for (int e = 0; e < 4; ++e) acc[nt][e] = 0.f;

#pragma unroll
        for (int np = 0; np < 8; ++np) {  // pairs of n-tiles
#pragma unroll
            for (int k = 0; k < 4; ++k) {
                uint32_t Bh[4], Bl[4];
                uint32_t ba = sb + SM_BH + b_lane_off +
                              (uint32_t)(np * 16 * PITCHB) + (uint32_t)(k * 32);
                ldsm4(Bh, ba);
                ldsm4(Bl, ba + (SM_BL - SM_BH));
                // pass hh, hl, lh for both n-tiles of the pair
                mma16816(acc[2 * np],     Ah[k], Bh + 0);
                mma16816(acc[2 * np],     Ah[k], Bl + 0);
                mma16816(acc[2 * np],     Al[k], Bh + 0);
                mma16816(acc[2 * np + 1], Ah[k], Bh + 2);
                mma16816(acc[2 * np + 1], Ah[k], Bl + 2);
                mma16816(acc[2 * np + 1], Al[k], Bh + 2);
            }
        }

        // ---- selection: 16 n-tiles x (2 rows x 2 cols) per lane ----
#pragma unroll
        for (int nt = 0; nt < 16; ++nt) {
            const int c0  = nt * 8 + tg * 2;
            const float cn0 = cn[c0], cn1 = cn[c0 + 1];
            const int gc0 = tt * TN + c0;
            float d;
            d = fmaf(-2.f, acc[nt][0], qn0 + cn0); INSERT(tk0, d, gc0);
            d = fmaf(-2.f, acc[nt][1], qn0 + cn1); INSERT(tk0, d, gc0 + 1);
            d = fmaf(-2.f, acc[nt][2], qn1 + cn0); INSERT(tk1, d, gc0);
            d = fmaf(-2.f, acc[nt][3], qn1 + cn1); INSERT(tk1, d, gc0 + 1);
        }
    }

    // ---- merge 4 lanes per row via SMEM keys overlay ----
    __syncthreads();
    unsigned long long* keys = reinterpret_cast<unsigned long long*>(smem);
#pragma unroll
    for (int k = 0; k < KNN; ++k) {
        keys[((row0)     * 4 + tg) * KNN + k] = tk0[k];
        keys[((row0 + 8) * 4 + tg) * KNN + k] = tk1[k];
    }
    __syncthreads();

    if (tid < TM) {
        const int r   = tid;
        const int gqi = b * NP + qbase + r;
        const unsigned long long* L = keys + (size_t)r * 4 * KNN;
        float* od = out + (size_t)gqi * KNN;
        float* odst = out + OUTBLK + (size_t)gqi * KNN;
        float* osrc = out + 2 * OUTBLK + (size_t)gqi * KNN;
        const float fsrc = (float)gqi;
        int i0 = 0, i1 = 0, i2 = 0, i3 = 0;
#pragma unroll 1
        for (int k = 0; k < KNN; ++k) {
            unsigned long long h0 = L[i0];
            unsigned long long h1 = L[KNN + i1];
            unsigned long long h2 = L[2 * KNN + i2];
            unsigned long long h3 = L[3 * KNN + i3];
            unsigned long long m01 = h0 < h1 ? h0 : h1;
            unsigned long long m23 = h2 < h3 ? h2 : h3;
            unsigned long long m = m01 < m23 ? m01 : m23;
            if (m == h0) ++i0;
            else if (m == h1) ++i1;
            else if (m == h2) ++i2;
            else ++i3;
            uint32_t o = (uint32_t)(m >> 32);
            uint32_t msk = (o & 0x80000000u) ? 0x80000000u : 0xFFFFFFFFu;
            od[k] = __uint_as_float(o ^ msk);
            if (write_edges) {
                odst[k] = (float)((uint32_t)(m & 0xFFFFFFFFu) + b * NP);
                osrc[k] = fsrc;
            }
        }
    }
}

extern "C" void kernel_launch(void* const* d_in, const int* in_sizes, int n_in,
                              void* d_out, int out_size) {
    const float* h   = (const float*)d_in[0];
    float*       out = (float*)d_out;
    const int write_edges = (out_size >= 3 * OUTBLK) ? 1 : 0;

    cudaFuncSetAttribute(knn_kernel, cudaFuncAttributeMaxDynamicSharedMemorySize,
                         SM_TOT);

    prep_kernel<<<(NS * NP) / 256, 256>>>(h);
    dim3 grid(NP / TM, NS);
    knn_kernel<<<grid, 256, SM_TOT>>>(out, write_edges);
}

// round 9
// speedup vs baseline: 1.4035x; 1.4035x over previous
#include <cuda_runtime.h>
#include <cuda_fp16.h>
#include <cstdint>

// NearestNeighborGraph: 16 samples x 2048 points x 64 dims, K=16.
// Output (float32): [knn_dist | dst | src], each 16*2048*16.
//
// Phase A (per tile): fp16 2-term-split mma.sync Gram tile, distances folded
//   (qn+cn-2dot) and stored to a padded SMEM tile.
// Phase B (per tile): 256 threads scan half-rows from SMEM with float top-16
//   sorted-insert lists. Final 2-way merge per row via packed u64 ord-keys.

#define NS     16
#define NP     2048
#define DIMS   64
#define KNN    16
#define TM     128
#define TN     128
#define NTILES (NP / TN)
#define OUTBLK (NS * NP * KNN)

#define PITCHB 144           // A/B smem row pitch in bytes (9x16B, ldmatrix conflict-free)
#define PITCHQ 9             // uint4 per row
#define TILEQ  (TM * PITCHQ) // 1152 uint4 = 18432 B per term tile
#define DPITCH 132           // dist tile row pitch in floats (128+4)

// SMEM layout (bytes)
#define SM_AH  0
#define SM_AL  18432
#define SM_BH  36864
#define SM_BL  55296
#define SM_CN  73728
#define SM_D   74240                      // 128*132*4 = 67584
#define SM_TOT (SM_D + TM * DPITCH * 4)   // 141824

__device__ uint4 g_h16[NS * NP * PITCHQ];  // fp16 hi plane, 144B pitch
__device__ uint4 g_l16[NS * NP * PITCHQ];  // fp16 lo plane
__device__ float g_x2[NS * NP];            // fp32 norms

// ---------------- helpers ----------------
__device__ __forceinline__ uint32_t smem_u32(const void* p) {
    uint32_t a;
    asm("{ .reg .u64 t; cvta.to.shared.u64 t, %1; cvt.u32.u64 %0, t; }"
        : "=r"(a) : "l"(p));
    return a;
}

__device__ __forceinline__ void ldsm4(uint32_t* r, uint32_t addr) {
    asm volatile("ldmatrix.sync.aligned.m8n8.x4.shared.b16 {%0,%1,%2,%3}, [%4];"
                 : "=r"(r[0]), "=r"(r[1]), "=r"(r[2]), "=r"(r[3]) : "r"(addr));
}

__device__ __forceinline__ void mma16816(float* d, const uint32_t* a,
                                         const uint32_t* b) {
    asm volatile(
        "mma.sync.aligned.m16n8k16.row.col.f32.f16.f16.f32 "
        "{%0,%1,%2,%3}, {%4,%5,%6,%7}, {%8,%9}, {%0,%1,%2,%3};"
        : "+f"(d[0]), "+f"(d[1]), "+f"(d[2]), "+f"(d[3])
        : "r"(a[0]), "r"(a[1]), "r"(a[2]), "r"(a[3]), "r"(b[0]), "r"(b[1]));
}

__device__ __forceinline__ uint32_t pack_h2(__half lo, __half hi) {
    __half2 h = __halves2half2(lo, hi);  // lo in low 16 bits
    return *reinterpret_cast<uint32_t*>(&h);
}

// Float sorted insert; strict '<' + ascending scan order => stable ties
// toward the smaller index (lax.top_k semantics).
#define INSERTF(dval, idx) do {                                                \
    if ((dval) < dk[KNN - 1]) {                                                \
        dk[KNN - 1] = (dval);                                                  \
        ik[KNN - 1] = (idx);                                                   \
        _Pragma("unroll")                                                      \
        for (int _t = KNN - 1; _t > 0; --_t) {                                 \
            if (dk[_t] < dk[_t - 1]) {                                         \
                float _fd = dk[_t]; dk[_t] = dk[_t - 1]; dk[_t - 1] = _fd;     \
                int   _fi = ik[_t]; ik[_t] = ik[_t - 1]; ik[_t - 1] = _fi;     \
            }                                                                  \
        }                                                                      \
    }                                                                          \
} while (0)

// ---------------- prologue: fp16 split planes + norms ----------------
__global__ void __launch_bounds__(256) prep_kernel(const float* __restrict__ h) {
    int r = blockIdx.x * blockDim.x + threadIdx.x;
    if (r >= NS * NP) return;
    const float4* src = reinterpret_cast<const float4*>(h + (size_t)r * DIMS);
    float s = 0.f;
#pragma unroll
    for (int q = 0; q < 8; ++q) {
        float4 x0 = src[2 * q];
        float4 x1 = src[2 * q + 1];
        float f[8] = {x0.x, x0.y, x0.z, x0.w, x1.x, x1.y, x1.z, x1.w};
        uint32_t rh[4], rl[4];
#pragma unroll
        for (int e = 0; e < 4; ++e) {
            float a = f[2 * e], c = f[2 * e + 1];
            __half ah = __float2half_rn(a), ch = __float2half_rn(c);
            float al = a - __half2float(ah);
            float cl = c - __half2float(ch);
            rh[e] = pack_h2(ah, ch);
            rl[e] = pack_h2(__float2half_rn(al), __float2half_rn(cl));
            s += a * a;
            s += c * c;
        }
        g_h16[(size_t)r * PITCHQ + q] = make_uint4(rh[0], rh[1], rh[2], rh[3]);
        g_l16[(size_t)r * PITCHQ + q] = make_uint4(rl[0], rl[1], rl[2], rl[3]);
    }
    g_h16[(size_t)r * PITCHQ + 8] = make_uint4(0, 0, 0, 0);
    g_l16[(size_t)r * PITCHQ + 8] = make_uint4(0, 0, 0, 0);
    g_x2[r] = s;
}

// ---------------- main kernel ----------------
__global__ void __launch_bounds__(256) knn_kernel(float* __restrict__ out,
                                                  int write_edges) {
    extern __shared__ char smem[];
    const uint32_t sb = smem_u32(smem);
    float* distf = reinterpret_cast<float*>(smem + SM_D);
    const int tid  = threadIdx.x;
    const int w    = tid >> 5;
    const int lane = tid & 31;
    const int tg   = lane & 3;   // col selector within mma tile
    const int g    = lane >> 2;  // row selector within mma tile
    const int b    = blockIdx.y;
    const int qbase = blockIdx.x * TM;

    // ---- stage A (query) tiles ----
    {
        const uint4* srcH = g_h16 + (size_t)(b * NP + qbase) * PITCHQ;
        const uint4* srcL = g_l16 + (size_t)(b * NP + qbase) * PITCHQ;
        uint4* dA = reinterpret_cast<uint4*>(smem);
        for (int i = tid; i < TILEQ; i += 256) {
            dA[i]         = srcH[i];
            dA[TILEQ + i] = srcL[i];
        }
    }
    __syncthreads();

    // ---- cache A fragments (fixed for whole CTA) ----
    uint32_t Ah[4][4], Al[4][4];
    {
        uint32_t a_off = sb + SM_AH + (uint32_t)(w * 16 + (lane & 15)) * PITCHB +
                         (uint32_t)(lane >> 4) * 16;
#pragma unroll
        for (int k = 0; k < 4; ++k) {
            ldsm4(Ah[k], a_off + k * 32);
            ldsm4(Al[k], a_off + (SM_AL - SM_AH) + k * 32);
        }
    }
    const int row0 = w * 16 + g;
    const float qn0 = g_x2[b * NP + qbase + row0];
    const float qn1 = g_x2[b * NP + qbase + row0 + 8];

    // ---- scan thread state: half a row each ----
    const int srow = tid >> 1;
    const int shb  = tid & 1;
    float dk[KNN];
    int   ik[KNN];
#pragma unroll
    for (int k = 0; k < KNN; ++k) { dk[k] = 3.4e38f; ik[k] = 0; }

    const uint32_t b_lane_off =
        (uint32_t)(((lane & 7) + ((lane >> 4) << 3)) * PITCHB) +
        ((lane & 8) ? 16u : 0u);
    const float* cn = reinterpret_cast<const float*>(smem + SM_CN);

    for (int tt = 0; tt < NTILES; ++tt) {
        __syncthreads();  // prev scan done (dist reusable), prev MMA B-reads done
        {
            const uint4* sH = g_h16 + (size_t)(b * NP + tt * TN) * PITCHQ;
            const uint4* sL = g_l16 + (size_t)(b * NP + tt * TN) * PITCHQ;
            uint4* dB = reinterpret_cast<uint4*>(smem + SM_BH);
            for (int i = tid; i < TILEQ; i += 256) {
                dB[i]         = sH[i];
                dB[TILEQ + i] = sL[i];
            }
            if (tid < TN)
                reinterpret_cast<float*>(smem + SM_CN)[tid] =
                    g_x2[b * NP + tt * TN + tid];
        }
        __syncthreads();

        // ---- Phase A: MMA + fold + store distances ----
        float acc[16][4];
#pragma unroll
        for (int nt = 0; nt < 16; ++nt)
#pragma unroll
            for (int e = 0; e < 4; ++e) acc[nt][e] = 0.f;

#pragma unroll
        for (int np = 0; np < 8; ++np) {
#pragma unroll
            for (int k = 0; k < 4; ++k) {
                uint32_t Bh[4], Bl[4];
                uint32_t ba = sb + SM_BH + b_lane_off +
                              (uint32_t)(np * 16 * PITCHB) + (uint32_t)(k * 32);
                ldsm4(Bh, ba);
                ldsm4(Bl, ba + (SM_BL - SM_BH));
                mma16816(acc[2 * np],     Ah[k], Bh + 0);
                mma16816(acc[2 * np],     Ah[k], Bl + 0);
                mma16816(acc[2 * np],     Al[k], Bh + 0);
                mma16816(acc[2 * np + 1], Ah[k], Bh + 2);
                mma16816(acc[2 * np + 1], Ah[k], Bl + 2);
                mma16816(acc[2 * np + 1], Al[k], Bh + 2);
            }
        }
#pragma unroll
        for (int nt = 0; nt < 16; ++nt) {
            const int c0 = nt * 8 + tg * 2;
            float2 cnp = *reinterpret_cast<const float2*>(cn + c0);
            float2 d0, d1;
            d0.x = fmaf(-2.f, acc[nt][0], qn0 + cnp.x);
            d0.y = fmaf(-2.f, acc[nt][1], qn0 + cnp.y);
            d1.x = fmaf(-2.f, acc[nt][2], qn1 + cnp.x);
            d1.y = fmaf(-2.f, acc[nt][3], qn1 + cnp.y);
            *reinterpret_cast<float2*>(distf + (size_t)row0 * DPITCH + c0)       = d0;
            *reinterpret_cast<float2*>(distf + (size_t)(row0 + 8) * DPITCH + c0) = d1;
        }
        __syncthreads();

        // ---- Phase B: scan half-row from SMEM ----
        const float4* drow = reinterpret_cast<const float4*>(
            distf + (size_t)srow * DPITCH + shb * 64);
        const int base = tt * TN + shb * 64;
#pragma unroll 1
        for (int j4 = 0; j4 < 16; ++j4) {
            float4 v = drow[j4];
            const int idx = base + j4 * 4;
            INSERTF(v.x, idx);
            INSERTF(v.y, idx + 1);
            INSERTF(v.z, idx + 2);
            INSERTF(v.w, idx + 3);
        }
    }

    // ---- merge 2 half-row lists per row via u64 ord-keys ----
    __syncthreads();
    unsigned long long* keys = reinterpret_cast<unsigned long long*>(smem + SM_D);
#pragma unroll
    for (int k = 0; k < KNN; ++k) {
        uint32_t u = __float_as_uint(dk[k]);
        u ^= (uint32_t)((int)u >> 31) | 0x80000000u;
        keys[((size_t)srow * 2 + shb) * KNN + k] =
            ((unsigned long long)u << 32) | (uint32_t)ik[k];
    }
    __syncthreads();

    if (tid < TM) {
        const int r   = tid;
        const int gqi = b * NP + qbase + r;
        const unsigned long long* L = keys + (size_t)r * 2 * KNN;
        float* od   = out + (size_t)gqi * KNN;
        float* odst = out + OUTBLK + (size_t)gqi * KNN;
        float* osrc = out + 2 * OUTBLK + (size_t)gqi * KNN;
        const float fsrc = (float)gqi;
        int i0 = 0, i1 = 0;
#pragma unroll 1
        for (int k = 0; k < KNN; ++k) {
            unsigned long long h0 = (i0 < KNN) ? L[i0] : ~0ull;
            unsigned long long h1 = (i1 < KNN) ? L[KNN + i1] : ~0ull;
            unsigned long long m;
            if (h0 <= h1) { m = h0; ++i0; } else { m = h1; ++i1; }
            uint32_t o = (uint32_t)(m >> 32);
            uint32_t msk = (o & 0x80000000u) ? 0x80000000u : 0xFFFFFFFFu;
            od[k] = __uint_as_float(o ^ msk);
            if (write_edges) {
                odst[k] = (float)((uint32_t)(m & 0xFFFFFFFFu) + b * NP);
                osrc[k] = fsrc;
            }
        }
    }
}

extern "C" void kernel_launch(void* const* d_in, const int* in_sizes, int n_in,
                              void* d_out, int out_size) {
    const float* h   = (const float*)d_in[0];
    float*       out = (float*)d_out;
    const int write_edges = (out_size >= 3 * OUTBLK) ? 1 : 0;

    cudaFuncSetAttribute(knn_kernel, cudaFuncAttributeMaxDynamicSharedMemorySize,
                         SM_TOT);

    prep_kernel<<<(NS * NP) / 256, 256>>>(h);
    dim3 grid(NP / TM, NS);
    knn_kernel<<<grid, 256, SM_TOT>>>(out, write_edges);
}

// round 10
// speedup vs baseline: 1.8601x; 1.3253x over previous
#include <cuda_runtime.h>
#include <cuda_fp16.h>
#include <cstdint>

// NearestNeighborGraph: 16 samples x 2048 points x 64 dims, K=16.
// Output (float32): [knn_dist | dst | src], each 16*2048*16.
//
// fp16 2-term-split mma.sync Gram tiles; distances folded and staged through
// two SMEM half-tiles; float top-16 sorted-insert scan with min4 pre-filter.
// SMEM 104.5KB + 128 regs => 2 CTAs/SM (16 warps resident).

#define NS     16
#define NP     2048
#define DIMS   64
#define KNN    16
#define TM     128
#define TN     128
#define NTILES (NP / TN)
#define OUTBLK (NS * NP * KNN)

#define PITCHB 144           // A/B smem row pitch bytes (9x16B, ldmatrix conflict-free)
#define PITCHQ 9             // uint4 per row
#define TILEQ  (TM * PITCHQ) // 1152 uint4 = 18432 B per term tile
#define DPITCH 68            // dist half-tile row pitch in floats (64+4)

// SMEM layout (bytes). A is staged in the B region pre-loop (dead after
// fragment load), so only B + two dist half-buffers + cn are resident.
#define SM_B   0
#define SM_BH  0
#define SM_BL  18432
#define SM_D0  36864
#define SM_D1  (SM_D0 + TM * DPITCH * 4)   // 71680
#define SM_CN  (SM_D1 + TM * DPITCH * 4)   // 106496
#define SM_TOT (SM_CN + 512)               // 107008

__device__ uint4 g_h16[NS * NP * PITCHQ];  // fp16 hi plane, 144B pitch
__device__ uint4 g_l16[NS * NP * PITCHQ];  // fp16 lo plane
__device__ float g_x2[NS * NP];            // fp32 norms

// ---------------- helpers ----------------
__device__ __forceinline__ uint32_t smem_u32(const void* p) {
    uint32_t a;
    asm("{ .reg .u64 t; cvta.to.shared.u64 t, %1; cvt.u32.u64 %0, t; }"
        : "=r"(a) : "l"(p));
    return a;
}

__device__ __forceinline__ void ldsm4(uint32_t* r, uint32_t addr) {
    asm volatile("ldmatrix.sync.aligned.m8n8.x4.shared.b16 {%0,%1,%2,%3}, [%4];"
                 : "=r"(r[0]), "=r"(r[1]), "=r"(r[2]), "=r"(r[3]) : "r"(addr));
}

__device__ __forceinline__ void mma16816(float* d, const uint32_t* a,
                                         const uint32_t* b) {
    asm volatile(
        "mma.sync.aligned.m16n8k16.row.col.f32.f16.f16.f32 "
        "{%0,%1,%2,%3}, {%4,%5,%6,%7}, {%8,%9}, {%0,%1,%2,%3};"
        : "+f"(d[0]), "+f"(d[1]), "+f"(d[2]), "+f"(d[3])
        : "r"(a[0]), "r"(a[1]), "r"(a[2]), "r"(a[3]), "r"(b[0]), "r"(b[1]));
}

__device__ __forceinline__ uint32_t pack_h2(__half lo, __half hi) {
    __half2 h = __halves2half2(lo, hi);
    return *reinterpret_cast<uint32_t*>(&h);
}

// Float sorted insert; strict '<' + increasing scan order per thread => stable
// ties toward the smaller index (lax.top_k semantics).
#define INSERTF(dval, idx) do {                                                \
    if ((dval) < dk[KNN - 1]) {                                                \
        dk[KNN - 1] = (dval);                                                  \
        ik[KNN - 1] = (idx);                                                   \
        _Pragma("unroll")                                                      \
        for (int _t = KNN - 1; _t > 0; --_t) {                                 \
            if (dk[_t] < dk[_t - 1]) {                                         \
                float _fd = dk[_t]; dk[_t] = dk[_t - 1]; dk[_t - 1] = _fd;     \
                int   _fi = ik[_t]; ik[_t] = ik[_t - 1]; ik[_t - 1] = _fi;     \
            }                                                                  \
        }                                                                      \
    }                                                                          \
} while (0)

// ---------------- prologue: fp16 split planes + norms ----------------
__global__ void __launch_bounds__(256) prep_kernel(const float* __restrict__ h) {
    int r = blockIdx.x * blockDim.x + threadIdx.x;
    if (r >= NS * NP) return;
    const float4* src = reinterpret_cast<const float4*>(h + (size_t)r * DIMS);
    float s = 0.f;
#pragma unroll
    for (int q = 0; q < 8; ++q) {
        float4 x0 = src[2 * q];
        float4 x1 = src[2 * q + 1];
        float f[8] = {x0.x, x0.y, x0.z, x0.w, x1.x, x1.y, x1.z, x1.w};
        uint32_t rh[4], rl[4];
#pragma unroll
        for (int e = 0; e < 4; ++e) {
            float a = f[2 * e], c = f[2 * e + 1];
            __half ah = __float2half_rn(a), ch = __float2half_rn(c);
            float al = a - __half2float(ah);
            float cl = c - __half2float(ch);
            rh[e] = pack_h2(ah, ch);
            rl[e] = pack_h2(__float2half_rn(al), __float2half_rn(cl));
            s += a * a;
            s += c * c;
        }
        g_h16[(size_t)r * PITCHQ + q] = make_uint4(rh[0], rh[1], rh[2], rh[3]);
        g_l16[(size_t)r * PITCHQ + q] = make_uint4(rl[0], rl[1], rl[2], rl[3]);
    }
    g_h16[(size_t)r * PITCHQ + 8] = make_uint4(0, 0, 0, 0);
    g_l16[(size_t)r * PITCHQ + 8] = make_uint4(0, 0, 0, 0);
    g_x2[r] = s;
}

// ---------------- main kernel ----------------
__global__ void __launch_bounds__(256, 2) knn_kernel(float* __restrict__ out,
                                                     int write_edges) {
    extern __shared__ char smem[];
    const uint32_t sb = smem_u32(smem);
    const int tid  = threadIdx.x;
    const int w    = tid >> 5;
    const int lane = tid & 31;
    const int tg   = lane & 3;   // col selector within mma tile
    const int g    = lane >> 2;  // row selector within mma tile
    const int b    = blockIdx.y;
    const int qbase = blockIdx.x * TM;

    // ---- stage A (query) tiles into the B region (dead after frag load) ----
    {
        const uint4* srcH = g_h16 + (size_t)(b * NP + qbase) * PITCHQ;
        const uint4* srcL = g_l16 + (size_t)(b * NP + qbase) * PITCHQ;
        uint4* dA = reinterpret_cast<uint4*>(smem + SM_B);
        for (int i = tid; i < TILEQ; i += 256) {
            dA[i]         = srcH[i];
            dA[TILEQ + i] = srcL[i];
        }
    }
    __syncthreads();

    // ---- cache A fragments (fixed for whole CTA) ----
    uint32_t Ah[4][4], Al[4][4];
    {
        uint32_t a_off = sb + SM_BH + (uint32_t)(w * 16 + (lane & 15)) * PITCHB +
                         (uint32_t)(lane >> 4) * 16;
#pragma unroll
        for (int k = 0; k < 4; ++k) {
            ldsm4(Ah[k], a_off + k * 32);
            ldsm4(Al[k], a_off + (SM_BL - SM_BH) + k * 32);
        }
    }
    const int row0 = w * 16 + g;
    const float qn0 = g_x2[b * NP + qbase + row0];
    const float qn1 = g_x2[b * NP + qbase + row0 + 8];

    // ---- scan thread state: half a row each (cols shb*32 of each half) ----
    const int srow = tid >> 1;
    const int shb  = tid & 1;
    float dk[KNN];
    int   ik[KNN];
#pragma unroll
    for (int k = 0; k < KNN; ++k) { dk[k] = 3.4e38f; ik[k] = 0; }

    const uint32_t b_lane_off =
        (uint32_t)(((lane & 7) + ((lane >> 4) << 3)) * PITCHB) +
        ((lane & 8) ? 16u : 0u);
    const float* cn = reinterpret_cast<const float*>(smem + SM_CN);

    for (int tt = 0; tt < NTILES; ++tt) {
        __syncthreads();  // prev tile scan + A-frag load done: B region reusable
        {
            const uint4* sH = g_h16 + (size_t)(b * NP + tt * TN) * PITCHQ;
            const uint4* sL = g_l16 + (size_t)(b * NP + tt * TN) * PITCHQ;
            uint4* dB = reinterpret_cast<uint4*>(smem + SM_B);
            for (int i = tid; i < TILEQ; i += 256) {
                dB[i]         = sH[i];
                dB[TILEQ + i] = sL[i];
            }
            if (tid < TN)
                reinterpret_cast<float*>(smem + SM_CN)[tid] =
                    g_x2[b * NP + tt * TN + tid];
        }
        __syncthreads();

        // ---- Phase A: MMA + fold + store, one n-half (64 cols) at a time ----
#pragma unroll 1
        for (int h = 0; h < 2; ++h) {
            float* distf = reinterpret_cast<float*>(smem + (h ? SM_D1 : SM_D0));
            float acc[8][4];
#pragma unroll
            for (int nt = 0; nt < 8; ++nt)
#pragma unroll
                for (int e = 0; e < 4; ++e) acc[nt][e] = 0.f;

#pragma unroll
            for (int np = 0; np < 4; ++np) {
#pragma unroll
                for (int k = 0; k < 4; ++k) {
                    uint32_t Bh[4], Bl[4];
                    uint32_t ba = sb + SM_BH + b_lane_off +
                                  (uint32_t)((h * 64 + np * 16) * PITCHB) +
                                  (uint32_t)(k * 32);
                    ldsm4(Bh, ba);
                    ldsm4(Bl, ba + (SM_BL - SM_BH));
                    mma16816(acc[2 * np],     Ah[k], Bh + 0);
                    mma16816(acc[2 * np],     Ah[k], Bl + 0);
                    mma16816(acc[2 * np],     Al[k], Bh + 0);
                    mma16816(acc[2 * np + 1], Ah[k], Bh + 2);
                    mma16816(acc[2 * np + 1], Ah[k], Bl + 2);
                    mma16816(acc[2 * np + 1], Al[k], Bh + 2);
                }
            }
#pragma unroll
            for (int nt = 0; nt < 8; ++nt) {
                const int c0 = nt * 8 + tg * 2;  // col within half
                float2 cnp = *reinterpret_cast<const float2*>(cn + h * 64 + c0);
                float2 d0, d1;
                d0.x = fmaf(-2.f, acc[nt][0], qn0 + cnp.x);
                d0.y = fmaf(-2.f, acc[nt][1], qn0 + cnp.y);
                d1.x = fmaf(-2.f, acc[nt][2], qn1 + cnp.x);
                d1.y = fmaf(-2.f, acc[nt][3], qn1 + cnp.y);
                *reinterpret_cast<float2*>(distf + (size_t)row0 * DPITCH + c0) = d0;
                *reinterpret_cast<float2*>(distf + (size_t)(row0 + 8) * DPITCH + c0) = d1;
            }
        }
        __syncthreads();  // both dist halves ready

        // ---- Phase B: scan this thread's 32-col chunk of each half ----
#pragma unroll 1
        for (int h = 0; h < 2; ++h) {
            const float4* drow = reinterpret_cast<const float4*>(
                reinterpret_cast<float*>(smem + (h ? SM_D1 : SM_D0)) +
                (size_t)srow * DPITCH + shb * 32);
            const int base = tt * TN + h * 64 + shb * 32;
#pragma unroll 1
            for (int j4 = 0; j4 < 8; ++j4) {
                float4 v = drow[j4];
                float m = fminf(fminf(v.x, v.y), fminf(v.z, v.w));
                if (m < dk[KNN - 1]) {
                    const int idx = base + j4 * 4;
                    INSERTF(v.x, idx);
                    INSERTF(v.y, idx + 1);
                    INSERTF(v.z, idx + 2);
                    INSERTF(v.w, idx + 3);
                }
            }
        }
    }

    // ---- merge the 2 per-row lists via packed u64 ord-keys ----
    __syncthreads();
    unsigned long long* keys = reinterpret_cast<unsigned long long*>(smem);
#pragma unroll
    for (int k = 0; k < KNN; ++k) {
        uint32_t u = __float_as_uint(dk[k]);
        u ^= (uint32_t)((int)u >> 31) | 0x80000000u;
        keys[((size_t)srow * 2 + shb) * KNN + k] =
            ((unsigned long long)u << 32) | (uint32_t)ik[k];
    }
    __syncthreads();

    if (tid < TM) {
        const int r   = tid;
        const int gqi = b * NP + qbase + r;
        const unsigned long long* L = keys + (size_t)r * 2 * KNN;
        float* od   = out + (size_t)gqi * KNN;
        float* odst = out + OUTBLK + (size_t)gqi * KNN;
        float* osrc = out + 2 * OUTBLK + (size_t)gqi * KNN;
        const float fsrc = (float)gqi;
        int i0 = 0, i1 = 0;
#pragma unroll 1
        for (int k = 0; k < KNN; ++k) {
            unsigned long long h0 = (i0 < KNN) ? L[i0] : ~0ull;
            unsigned long long h1 = (i1 < KNN) ? L[KNN + i1] : ~0ull;
            unsigned long long m;
            if (h0 <= h1) { m = h0; ++i0; } else { m = h1; ++i1; }
            uint32_t o = (uint32_t)(m >> 32);
            uint32_t msk = (o & 0x80000000u) ? 0x80000000u : 0xFFFFFFFFu;
            od[k] = __uint_as_float(o ^ msk);
            if (write_edges) {
                odst[k] = (float)((uint32_t)(m & 0xFFFFFFFFu) + b * NP);
                osrc[k] = fsrc;
            }
        }
    }
}

extern "C" void kernel_launch(void* const* d_in, const int* in_sizes, int n_in,
                              void* d_out, int out_size) {
    const float* h   = (const float*)d_in[0];
    float*       out = (float*)d_out;
    const int write_edges = (out_size >= 3 * OUTBLK) ? 1 : 0;

    cudaFuncSetAttribute(knn_kernel, cudaFuncAttributeMaxDynamicSharedMemorySize,
                         SM_TOT);

    prep_kernel<<<(NS * NP) / 256, 256>>>(h);
    dim3 grid(NP / TM, NS);
    knn_kernel<<<grid, 256, SM_TOT>>>(out, write_edges);
}